// round 9
// baseline (speedup 1.0000x reference)
#include <cuda_runtime.h>
#include <cuda_bf16.h>

// ---------------- problem constants ----------------
#define T_SEQ   4096
#define D_MODEL 1024
#define NHEADS  16
#define NKV     4
#define HD      64
#define KVD     (NKV*HD)     // 256
#define WINDOW  256

// ---------------- scratch ----------------
__device__ float g_q[T_SEQ * D_MODEL];
__device__ float g_k[T_SEQ * KVD];
__device__ float g_v[T_SEQ * KVD];
__device__ float g_attn[T_SEQ * D_MODEL];

// ================= shared mma helpers =================
__device__ __forceinline__ void mma_bf16(float d[4], const unsigned a[4], const unsigned b[2])
{
    asm volatile(
        "mma.sync.aligned.m16n8k16.row.col.f32.bf16.bf16.f32 "
        "{%0,%1,%2,%3}, {%4,%5,%6,%7}, {%8,%9}, {%0,%1,%2,%3};\n"
        : "+f"(d[0]), "+f"(d[1]), "+f"(d[2]), "+f"(d[3])
        : "r"(a[0]), "r"(a[1]), "r"(a[2]), "r"(a[3]), "r"(b[0]), "r"(b[1]));
}

__device__ __forceinline__ void split2(float a, float b, unsigned& h, unsigned& l)
{
    __nv_bfloat16 ha = __float2bfloat16(a), hb = __float2bfloat16(b);
    __nv_bfloat16 la = __float2bfloat16(a - __bfloat162float(ha));
    __nv_bfloat16 lb = __float2bfloat16(b - __bfloat162float(hb));
    __nv_bfloat162 hh; hh.x = ha; hh.y = hb;
    __nv_bfloat162 ll; ll.x = la; ll.y = lb;
    h = *reinterpret_cast<unsigned*>(&hh);
    l = *reinterpret_cast<unsigned*>(&ll);
}

__device__ __forceinline__ unsigned lds_u32b(const __nv_bfloat16* p)
{
    return *reinterpret_cast<const unsigned*>(p);
}

__device__ __forceinline__ float ex2(float x)
{
    float r;
    asm("ex2.approx.ftz.f32 %0, %1;" : "=f"(r) : "f"(x));
    return r;
}

// ================= bf16-split tensor-core GEMM =================
// C = A@B + bias (fp32 in/out) via Ahi*Bhi + Ahi*Blo + Alo*Bhi bf16 mma.
// CTA tile 128x256, BK=16, 256 threads = 8 warps (2x4), warp tile 64x64.
// LDS:mma ratio 64:96 (was 48:48) -> attacks the measured smem-BW bound.
#define GBM 128
#define GBN 256
#define GBK 16
#define GSTR 24   // bf16 elements per smem row (48B, conflict-free)

struct SmemGemm {
    __nv_bfloat16 Ah[GBM * GSTR];   // 6 KB
    __nv_bfloat16 Al[GBM * GSTR];   // 6 KB
    __nv_bfloat16 Bh[GBN * GSTR];   // 12 KB
    __nv_bfloat16 Bl[GBN * GSTR];   // 12 KB -> 36 KB total
};

__device__ __forceinline__ void split8(const float* x, unsigned h[4], unsigned l[4])
{
#pragma unroll
    for (int p = 0; p < 4; p++) split2(x[2 * p], x[2 * p + 1], h[p], l[p]);
}

__device__ __forceinline__ void gemm_body(
    const float* __restrict__ A, const float* __restrict__ B,
    const float* __restrict__ bias, float* __restrict__ C,
    int N, int K, int bx, int by, SmemGemm* sm)
{
    const int tid  = threadIdx.x;
    const int wid  = tid >> 5;
    const int lane = tid & 31;
    const int gid  = lane >> 2;   // 0..7
    const int tig  = lane & 3;    // 0..3
    const int wm   = wid & 1;     // 2 warps along M (64 rows each)
    const int wn   = wid >> 1;    // 4 warps along N (64 cols each)

    // A global mapping: row = tid>>1, k0 = (tid&1)*8
    const int arow = tid >> 1;
    const int ak0  = (tid & 1) * 8;
    // B global mapping: n = tid, all 16 k
    const int bn   = tid;

    const float* Ap = A + (size_t)(by * GBM + arow) * K + ak0;
    const float* Bp = B + bx * GBN + bn;

    float acc[4][8][4];
#pragma unroll
    for (int i = 0; i < 4; i++)
#pragma unroll
        for (int j = 0; j < 8; j++)
#pragma unroll
            for (int r = 0; r < 4; r++) acc[i][j][r] = 0.f;

    float ar[8], br[16];
    // prologue: tile 0 global -> regs
    {
        float4 v0 = *(const float4*)(Ap);
        float4 v1 = *(const float4*)(Ap + 4);
        ar[0]=v0.x; ar[1]=v0.y; ar[2]=v0.z; ar[3]=v0.w;
        ar[4]=v1.x; ar[5]=v1.y; ar[6]=v1.z; ar[7]=v1.w;
#pragma unroll
        for (int i = 0; i < 16; i++) br[i] = Bp[(size_t)i * N];
    }

    const int nk = K / GBK;
    for (int t = 0; t < nk; t++) {
        // stage regs -> smem
        {
            unsigned h[4], l[4];
            split8(ar, h, l);
            *(uint4*)&sm->Ah[arow * GSTR + ak0] = make_uint4(h[0], h[1], h[2], h[3]);
            *(uint4*)&sm->Al[arow * GSTR + ak0] = make_uint4(l[0], l[1], l[2], l[3]);
            unsigned h2[8], l2[8];
#pragma unroll
            for (int p = 0; p < 8; p++) split2(br[2*p], br[2*p+1], h2[p], l2[p]);
            *(uint4*)&sm->Bh[bn * GSTR + 0] = make_uint4(h2[0], h2[1], h2[2], h2[3]);
            *(uint4*)&sm->Bh[bn * GSTR + 8] = make_uint4(h2[4], h2[5], h2[6], h2[7]);
            *(uint4*)&sm->Bl[bn * GSTR + 0] = make_uint4(l2[0], l2[1], l2[2], l2[3]);
            *(uint4*)&sm->Bl[bn * GSTR + 8] = make_uint4(l2[4], l2[5], l2[6], l2[7]);
        }
        __syncthreads();

        // prefetch next tile globals (overlaps mma)
        const bool more = (t + 1 < nk);
        if (more) {
            const float* Ap2 = Ap + (t + 1) * GBK;
            const float* Bp2 = Bp + (size_t)(t + 1) * GBK * N;
            float4 v0 = *(const float4*)(Ap2);
            float4 v1 = *(const float4*)(Ap2 + 4);
            ar[0]=v0.x; ar[1]=v0.y; ar[2]=v0.z; ar[3]=v0.w;
            ar[4]=v1.x; ar[5]=v1.y; ar[6]=v1.z; ar[7]=v1.w;
#pragma unroll
            for (int i = 0; i < 16; i++) br[i] = Bp2[(size_t)i * N];
        }

        // B fragments for the whole 64-col warp tile
        unsigned bh[8][2], bl[8][2];
#pragma unroll
        for (int j = 0; j < 8; j++) {
            const int n0 = wn * 64 + j * 8 + gid;
            bh[j][0] = lds_u32b(&sm->Bh[n0 * GSTR + tig * 2    ]);
            bh[j][1] = lds_u32b(&sm->Bh[n0 * GSTR + tig * 2 + 8]);
            bl[j][0] = lds_u32b(&sm->Bl[n0 * GSTR + tig * 2    ]);
            bl[j][1] = lds_u32b(&sm->Bl[n0 * GSTR + tig * 2 + 8]);
        }
        // A fragments per 16-row block, interleaved with mma
#pragma unroll
        for (int i = 0; i < 4; i++) {
            const int r0 = wm * 64 + i * 16 + gid;
            unsigned ah[4], al[4];
            ah[0] = lds_u32b(&sm->Ah[(r0    ) * GSTR + tig * 2    ]);
            ah[1] = lds_u32b(&sm->Ah[(r0 + 8) * GSTR + tig * 2    ]);
            ah[2] = lds_u32b(&sm->Ah[(r0    ) * GSTR + tig * 2 + 8]);
            ah[3] = lds_u32b(&sm->Ah[(r0 + 8) * GSTR + tig * 2 + 8]);
            al[0] = lds_u32b(&sm->Al[(r0    ) * GSTR + tig * 2    ]);
            al[1] = lds_u32b(&sm->Al[(r0 + 8) * GSTR + tig * 2    ]);
            al[2] = lds_u32b(&sm->Al[(r0    ) * GSTR + tig * 2 + 8]);
            al[3] = lds_u32b(&sm->Al[(r0 + 8) * GSTR + tig * 2 + 8]);
#pragma unroll
            for (int j = 0; j < 8; j++) {
                mma_bf16(acc[i][j], ah, bh[j]);
                mma_bf16(acc[i][j], ah, bl[j]);
                mma_bf16(acc[i][j], al, bh[j]);
            }
        }
        __syncthreads();
    }

    // epilogue: bias + store
#pragma unroll
    for (int i = 0; i < 4; i++) {
        const int row = by * GBM + wm * 64 + i * 16 + gid;
#pragma unroll
        for (int j = 0; j < 8; j++) {
            const int col = bx * GBN + wn * 64 + j * 8 + tig * 2;
            const float b0 = bias[col], b1 = bias[col + 1];
            float2 s0 = make_float2(acc[i][j][0] + b0, acc[i][j][1] + b1);
            float2 s1 = make_float2(acc[i][j][2] + b0, acc[i][j][3] + b1);
            *(float2*)&C[(size_t)row * N + col]       = s0;
            *(float2*)&C[(size_t)(row + 8) * N + col] = s1;
        }
    }
}

// out-projection: C(4096x1024) = attn @ Wo + bo
__global__ __launch_bounds__(256, 1) void gemm_tc(
    const float* __restrict__ A, const float* __restrict__ B,
    const float* __restrict__ bias, float* __restrict__ C, int N, int K)
{
    __shared__ SmemGemm sm;
    gemm_body(A, B, bias, C, N, K, blockIdx.x, blockIdx.y, &sm);
}

// fused Q + K + V projections in one launch (shared A = x).
// grid.x: 0..3 -> Q column tiles; 4 -> K; 5 -> V.
__global__ __launch_bounds__(256, 1) void gemm_qkv(
    const float* __restrict__ x,
    const float* __restrict__ Wq, const float* __restrict__ bq,
    const float* __restrict__ Wk, const float* __restrict__ bk,
    const float* __restrict__ Wv, const float* __restrict__ bv)
{
    __shared__ SmemGemm sm;
    const int bx = blockIdx.x;
    const float* B; const float* bias; float* C; int N; int bxe;
    if (bx < 4)      { B = Wq; bias = bq; C = g_q; N = D_MODEL; bxe = bx; }
    else if (bx == 4){ B = Wk; bias = bk; C = g_k; N = KVD;     bxe = 0;  }
    else             { B = Wv; bias = bv; C = g_v; N = KVD;     bxe = 0;  }
    gemm_body(x, B, bias, C, N, D_MODEL, bxe, blockIdx.y, &sm);
}

// ================= tensor-core flash attention (windowed, ALiBi, GQA) =================
// (unchanged from R4 — proven correct; target of a later round)
#define ASTR 72

__global__ __launch_bounds__(256) void attn_tc(
    const float* __restrict__ Q, const float* __restrict__ Kg,
    const float* __restrict__ Vg, float* __restrict__ Og)
{
    __shared__ __nv_bfloat16 smKh[64 * ASTR];
    __shared__ __nv_bfloat16 smKl[64 * ASTR];
    __shared__ __nv_bfloat16 smVh[64 * ASTR];   // transposed [d][key]
    __shared__ __nv_bfloat16 smVl[64 * ASTR];

    const int h   = blockIdx.y;
    const int qb  = blockIdx.x * 128;
    const int tid = threadIdx.x;
    const int wid = tid >> 5;
    const int lane = tid & 31;
    const int gid = lane >> 2;
    const int tig = lane & 3;
    const int qw0 = wid * 16;
    const int kvh = h >> 2;
    const float slope2 = exp2f(-0.5f * (float)(h + 1)) * 1.442695041f;
    const float qscale = 0.125f * 1.442695041f;

    // stage Q (128x64), pre-scaled, into K/V smem space temporarily
    {
        __nv_bfloat16* Qh = smKh;
        __nv_bfloat16* Ql = smVh;
        for (int u = tid; u < 128 * 16; u += 256) {
            const int r  = u >> 4;
            const int d4 = (u & 15) << 2;
            float4 v = *(const float4*)(Q + (size_t)(qb + r) * D_MODEL + h * HD + d4);
            unsigned h0, l0, h1, l1;
            split2(v.x * qscale, v.y * qscale, h0, l0);
            split2(v.z * qscale, v.w * qscale, h1, l1);
            *(uint2*)&Qh[r * ASTR + d4] = make_uint2(h0, h1);
            *(uint2*)&Ql[r * ASTR + d4] = make_uint2(l0, l1);
        }
        __syncthreads();
    }

    unsigned qh[4][4], ql[4][4];
    {
        const __nv_bfloat16* Qh = smKh;
        const __nv_bfloat16* Ql = smVh;
#pragma unroll
        for (int t = 0; t < 4; t++) {
            const int base = (qw0 + gid) * ASTR + 16 * t + 2 * tig;
            qh[t][0] = lds_u32b(&Qh[base]);
            qh[t][1] = lds_u32b(&Qh[base + 8 * ASTR]);
            qh[t][2] = lds_u32b(&Qh[base + 8]);
            qh[t][3] = lds_u32b(&Qh[base + 8 * ASTR + 8]);
            ql[t][0] = lds_u32b(&Ql[base]);
            ql[t][1] = lds_u32b(&Ql[base + 8 * ASTR]);
            ql[t][2] = lds_u32b(&Ql[base + 8]);
            ql[t][3] = lds_u32b(&Ql[base + 8 * ASTR + 8]);
        }
        __syncthreads();
    }

    float o[8][4];
#pragma unroll
    for (int j = 0; j < 8; j++)
#pragma unroll
        for (int r = 0; r < 4; r++) o[j][r] = 0.f;
    float lsum0 = 0.f, lsum1 = 0.f;

    const int qi0     = qb + qw0 + gid;
    const int q_first = qb + qw0;
    const int q_last  = q_first + 15;

    int kb0 = qb - WINDOW;
    if (kb0 < 0) kb0 = 0;
    const int kbend = qb + 128;

    for (int kb = kb0; kb < kbend; kb += 64) {
        for (int u = tid; u < 64 * 16; u += 256) {
            const int r  = u >> 4;
            const int d4 = (u & 15) << 2;
            float4 v = *(const float4*)(Kg + (size_t)(kb + r) * KVD + kvh * HD + d4);
            unsigned h0, l0, h1, l1;
            split2(v.x, v.y, h0, l0);
            split2(v.z, v.w, h1, l1);
            *(uint2*)&smKh[r * ASTR + d4] = make_uint2(h0, h1);
            *(uint2*)&smKl[r * ASTR + d4] = make_uint2(l0, l1);
        }
        for (int u = tid; u < 2048; u += 256) {
            const int d  = u & 63;
            const int kp = u >> 6;
            const float v0 = Vg[(size_t)(kb + 2 * kp)     * KVD + kvh * HD + d];
            const float v1 = Vg[(size_t)(kb + 2 * kp + 1) * KVD + kvh * HD + d];
            unsigned hh, ll;
            split2(v0, v1, hh, ll);
            *(unsigned*)&smVh[d * ASTR + 2 * kp] = hh;
            *(unsigned*)&smVl[d * ASTR + 2 * kp] = ll;
        }
        __syncthreads();

        const bool active = !(kb > q_last || kb + 63 < q_first - (WINDOW - 1));
        if (active) {
            unsigned ph[8][2], pl[8][2];
            const int dbase = qi0 - kb;
#pragma unroll
            for (int j = 0; j < 8; j++) {
                float s[4] = {0.f, 0.f, 0.f, 0.f};
#pragma unroll
                for (int t = 0; t < 4; t++) {
                    const int kbase = (8 * j + gid) * ASTR + 16 * t + 2 * tig;
                    unsigned bh[2], bl[2];
                    bh[0] = lds_u32b(&smKh[kbase]);
                    bh[1] = lds_u32b(&smKh[kbase + 8]);
                    bl[0] = lds_u32b(&smKl[kbase]);
                    bl[1] = lds_u32b(&smKl[kbase + 8]);
                    mma_bf16(s, qh[t], bh);
                    mma_bf16(s, qh[t], bl);
                    mma_bf16(s, ql[t], bh);
                }
                const int d00 = dbase - 8 * j - 2 * tig;
                const int d01 = d00 - 1, d10 = d00 + 8, d11 = d00 + 7;
                float p00 = ((unsigned)d00 < WINDOW) ? ex2(fmaf(-slope2, (float)d00, s[0])) : 0.f;
                float p01 = ((unsigned)d01 < WINDOW) ? ex2(fmaf(-slope2, (float)d01, s[1])) : 0.f;
                float p10 = ((unsigned)d10 < WINDOW) ? ex2(fmaf(-slope2, (float)d10, s[2])) : 0.f;
                float p11 = ((unsigned)d11 < WINDOW) ? ex2(fmaf(-slope2, (float)d11, s[3])) : 0.f;
                lsum0 += p00 + p01;
                lsum1 += p10 + p11;
                split2(p00, p01, ph[j][0], pl[j][0]);
                split2(p10, p11, ph[j][1], pl[j][1]);
            }

#pragma unroll
            for (int t = 0; t < 4; t++) {
                unsigned ah[4] = { ph[2*t][0], ph[2*t][1], ph[2*t+1][0], ph[2*t+1][1] };
                unsigned al[4] = { pl[2*t][0], pl[2*t][1], pl[2*t+1][0], pl[2*t+1][1] };
#pragma unroll
                for (int jd = 0; jd < 8; jd++) {
                    const int vbase = (8 * jd + gid) * ASTR + 16 * t + 2 * tig;
                    unsigned bh[2], bl[2];
                    bh[0] = lds_u32b(&smVh[vbase]);
                    bh[1] = lds_u32b(&smVh[vbase + 8]);
                    bl[0] = lds_u32b(&smVl[vbase]);
                    bl[1] = lds_u32b(&smVl[vbase + 8]);
                    mma_bf16(o[jd], ah, bh);
                    mma_bf16(o[jd], ah, bl);
                    mma_bf16(o[jd], al, bh);
                }
            }
        }
        __syncthreads();
    }

    lsum0 += __shfl_xor_sync(0xffffffffu, lsum0, 1);
    lsum0 += __shfl_xor_sync(0xffffffffu, lsum0, 2);
    lsum1 += __shfl_xor_sync(0xffffffffu, lsum1, 1);
    lsum1 += __shfl_xor_sync(0xffffffffu, lsum1, 2);
    const float inv0 = 1.f / lsum0;
    const float inv1 = 1.f / lsum1;

    const int row0 = qi0;
#pragma unroll
    for (int jd = 0; jd < 8; jd++) {
        const int col = h * HD + 8 * jd + 2 * tig;
        float2 s0 = make_float2(o[jd][0] * inv0, o[jd][1] * inv0);
        float2 s1 = make_float2(o[jd][2] * inv1, o[jd][3] * inv1);
        *(float2*)&Og[(size_t)row0 * D_MODEL + col]       = s0;
        *(float2*)&Og[(size_t)(row0 + 8) * D_MODEL + col] = s1;
    }
}

// ---------------- launch ----------------
extern "C" void kernel_launch(void* const* d_in, const int* in_sizes, int n_in,
                              void* d_out, int out_size)
{
    const float* x  = (const float*)d_in[0];
    const float* Wq = (const float*)d_in[1];
    const float* bq = (const float*)d_in[2];
    const float* Wk = (const float*)d_in[3];
    const float* bk = (const float*)d_in[4];
    const float* Wv = (const float*)d_in[5];
    const float* bv = (const float*)d_in[6];
    const float* Wo = (const float*)d_in[7];
    const float* bo = (const float*)d_in[8];
    float* out = (float*)d_out;

    float *q, *k, *v, *attn;
    cudaGetSymbolAddress((void**)&q,    g_q);
    cudaGetSymbolAddress((void**)&k,    g_k);
    cudaGetSymbolAddress((void**)&v,    g_v);
    cudaGetSymbolAddress((void**)&attn, g_attn);

    // fused Q+K+V projections: grid (6, 32)
    dim3 gQkv(6, T_SEQ / GBM);
    gemm_qkv<<<gQkv, 256>>>(x, Wq, bq, Wk, bk, Wv, bv);

    dim3 gAttn(T_SEQ / 128, NHEADS);         // (32, 16)
    attn_tc<<<gAttn, 256>>>(q, k, v, attn);

    // out projection: grid (4, 32)
    dim3 gOut(D_MODEL / GBN, T_SEQ / GBM);
    gemm_tc<<<gOut, 256>>>(attn, Wo, bo, out, D_MODEL, D_MODEL);
}

// round 10
// speedup vs baseline: 1.1815x; 1.1815x over previous
#include <cuda_runtime.h>
#include <cuda_bf16.h>

// ---------------- problem constants ----------------
#define T_SEQ   4096
#define D_MODEL 1024
#define NHEADS  16
#define NKV     4
#define HD      64
#define KVD     (NKV*HD)     // 256
#define WINDOW  256

// ---------------- scratch ----------------
__device__ float g_q[T_SEQ * D_MODEL];
__device__ float g_k[T_SEQ * KVD];
__device__ float g_v[T_SEQ * KVD];
__device__ float g_attn[T_SEQ * D_MODEL];

// ================= shared mma helpers =================
__device__ __forceinline__ void mma_bf16(float d[4], const unsigned a[4], const unsigned b[2])
{
    asm volatile(
        "mma.sync.aligned.m16n8k16.row.col.f32.bf16.bf16.f32 "
        "{%0,%1,%2,%3}, {%4,%5,%6,%7}, {%8,%9}, {%0,%1,%2,%3};\n"
        : "+f"(d[0]), "+f"(d[1]), "+f"(d[2]), "+f"(d[3])
        : "r"(a[0]), "r"(a[1]), "r"(a[2]), "r"(a[3]), "r"(b[0]), "r"(b[1]));
}

__device__ __forceinline__ void ldsm_x4(unsigned r[4], unsigned addr)
{
    asm volatile("ldmatrix.sync.aligned.m8n8.x4.shared.b16 {%0,%1,%2,%3}, [%4];"
                 : "=r"(r[0]), "=r"(r[1]), "=r"(r[2]), "=r"(r[3]) : "r"(addr));
}

__device__ __forceinline__ void split2(float a, float b, unsigned& h, unsigned& l)
{
    __nv_bfloat16 ha = __float2bfloat16(a), hb = __float2bfloat16(b);
    __nv_bfloat16 la = __float2bfloat16(a - __bfloat162float(ha));
    __nv_bfloat16 lb = __float2bfloat16(b - __bfloat162float(hb));
    __nv_bfloat162 hh; hh.x = ha; hh.y = hb;
    __nv_bfloat162 ll; ll.x = la; ll.y = lb;
    h = *reinterpret_cast<unsigned*>(&hh);
    l = *reinterpret_cast<unsigned*>(&ll);
}

__device__ __forceinline__ unsigned lds_u32b(const __nv_bfloat16* p)
{
    return *reinterpret_cast<const unsigned*>(p);
}

__device__ __forceinline__ float ex2(float x)
{
    float r;
    asm("ex2.approx.ftz.f32 %0, %1;" : "=f"(r) : "f"(x));
    return r;
}

// ================= bf16-split tensor-core GEMM =================
// R8-proven shape: CTA 128x128, BK=16, 8 warps (2x4), warp tile 64x32,
// double-buffered. NEW: fragment loads via ldmatrix.x4 (12 LDSM/tile vs 48 LDS).
#define GBM 128
#define GBN 128
#define GBK 16
#define GSTR 24   // bf16 elements per smem row (48B, conflict-free for LDSM)

struct SmemGemm {
    __nv_bfloat16 Ah[GBM * GSTR];
    __nv_bfloat16 Al[GBM * GSTR];
    __nv_bfloat16 Bh[GBN * GSTR];
    __nv_bfloat16 Bl[GBN * GSTR];
};

__device__ __forceinline__ void split8(const float* x, unsigned h[4], unsigned l[4])
{
#pragma unroll
    for (int p = 0; p < 4; p++) split2(x[2 * p], x[2 * p + 1], h[p], l[p]);
}

__device__ __forceinline__ void gemm_body(
    const float* __restrict__ A, const float* __restrict__ B,
    const float* __restrict__ bias, float* __restrict__ C,
    int N, int K, int bx, int by, SmemGemm* smbuf)
{
    const int tid  = threadIdx.x;
    const int wid  = tid >> 5;
    const int lane = tid & 31;
    const int gid  = lane >> 2;
    const int tig  = lane & 3;
    const int wm   = wid & 1;     // 2 warps along M
    const int wn   = wid >> 1;    // 4 warps along N

    const int arow = tid >> 1;
    const int ak0  = (tid & 1) * 8;
    const int bn   = tid & 127;
    const int bk0  = (tid >> 7) * 8;

    // ldmatrix lane-address patterns (see fragment spec):
    // A (16x16 tile): m0=rows0-7/cols0-7, m1=rows8-15/c0-7, m2=r0-7/c8-15, m3=r8-15/c8-15
    const int l7    = lane & 7;
    const int a_row = l7 + ((lane >> 3) & 1) * 8;
    const int a_col = (lane >> 4) * 8;
    // B (two 8n x 16k tiles): m0=n0-7/k0-7, m1=n0-7/k8-15, m2=n8-15/k0-7, m3=n8-15/k8-15
    const int b_row = l7 + (lane >> 4) * 8;
    const int b_col = ((lane >> 3) & 1) * 8;

    unsigned shAh[2], shAl[2], shBh[2], shBl[2];
#pragma unroll
    for (int bu = 0; bu < 2; bu++) {
        shAh[bu] = (unsigned)__cvta_generic_to_shared(smbuf[bu].Ah)
                 + ((wm * 64 + a_row) * GSTR + a_col) * 2;
        shAl[bu] = (unsigned)__cvta_generic_to_shared(smbuf[bu].Al)
                 + ((wm * 64 + a_row) * GSTR + a_col) * 2;
        shBh[bu] = (unsigned)__cvta_generic_to_shared(smbuf[bu].Bh)
                 + ((wn * 32 + b_row) * GSTR + b_col) * 2;
        shBl[bu] = (unsigned)__cvta_generic_to_shared(smbuf[bu].Bl)
                 + ((wn * 32 + b_row) * GSTR + b_col) * 2;
    }

    const float* Ap = A + (size_t)(by * GBM + arow) * K + ak0;
    const float* Bp = B + (size_t)bk0 * N + bx * GBN + bn;

    float acc[4][4][4];
#pragma unroll
    for (int i = 0; i < 4; i++)
#pragma unroll
        for (int j = 0; j < 4; j++)
#pragma unroll
            for (int r = 0; r < 4; r++) acc[i][j][r] = 0.f;

    float ar[8], br[8];
    // prologue: load tile 0, stage into buffer 0
    {
        float4 v0 = *(const float4*)(Ap);
        float4 v1 = *(const float4*)(Ap + 4);
        ar[0]=v0.x; ar[1]=v0.y; ar[2]=v0.z; ar[3]=v0.w;
        ar[4]=v1.x; ar[5]=v1.y; ar[6]=v1.z; ar[7]=v1.w;
#pragma unroll
        for (int i = 0; i < 8; i++) br[i] = Bp[(size_t)i * N];

        unsigned h[4], l[4];
        split8(ar, h, l);
        *(uint4*)&smbuf[0].Ah[arow * GSTR + ak0] = make_uint4(h[0], h[1], h[2], h[3]);
        *(uint4*)&smbuf[0].Al[arow * GSTR + ak0] = make_uint4(l[0], l[1], l[2], l[3]);
        split8(br, h, l);
        *(uint4*)&smbuf[0].Bh[bn * GSTR + bk0] = make_uint4(h[0], h[1], h[2], h[3]);
        *(uint4*)&smbuf[0].Bl[bn * GSTR + bk0] = make_uint4(l[0], l[1], l[2], l[3]);
    }
    __syncthreads();

    const int nk = K / GBK;
    for (int t = 0; t < nk; t++) {
        const int bu = t & 1;
        const bool more = (t + 1 < nk);
        if (more) {
            const float* Ap2 = Ap + (t + 1) * GBK;
            const float* Bp2 = Bp + (size_t)(t + 1) * GBK * N;
            float4 v0 = *(const float4*)(Ap2);
            float4 v1 = *(const float4*)(Ap2 + 4);
            ar[0]=v0.x; ar[1]=v0.y; ar[2]=v0.z; ar[3]=v0.w;
            ar[4]=v1.x; ar[5]=v1.y; ar[6]=v1.z; ar[7]=v1.w;
#pragma unroll
            for (int i = 0; i < 8; i++) br[i] = Bp2[(size_t)i * N];
        }

        // B fragments: 2 LDSM.x4 per precision -> bh[4][2], bl[4][2]
        unsigned bh[4][2], bl[4][2];
#pragma unroll
        for (int jp = 0; jp < 2; jp++) {
            const unsigned off = (unsigned)(jp * 16 * GSTR * 2);
            unsigned r[4];
            ldsm_x4(r, shBh[bu] + off);
            bh[2*jp][0] = r[0]; bh[2*jp][1] = r[1];
            bh[2*jp+1][0] = r[2]; bh[2*jp+1][1] = r[3];
            ldsm_x4(r, shBl[bu] + off);
            bl[2*jp][0] = r[0]; bl[2*jp][1] = r[1];
            bl[2*jp+1][0] = r[2]; bl[2*jp+1][1] = r[3];
        }
        // A fragments per 16-row block: 2 LDSM.x4, interleaved with mma
#pragma unroll
        for (int i = 0; i < 4; i++) {
            const unsigned off = (unsigned)(i * 16 * GSTR * 2);
            unsigned ah[4], al[4];
            ldsm_x4(ah, shAh[bu] + off);
            ldsm_x4(al, shAl[bu] + off);
#pragma unroll
            for (int j = 0; j < 4; j++) {
                mma_bf16(acc[i][j], ah, bh[j]);
                mma_bf16(acc[i][j], ah, bl[j]);
                mma_bf16(acc[i][j], al, bh[j]);
            }
        }

        if (more) {
            SmemGemm* sn = &smbuf[(t + 1) & 1];
            unsigned h[4], l[4];
            split8(ar, h, l);
            *(uint4*)&sn->Ah[arow * GSTR + ak0] = make_uint4(h[0], h[1], h[2], h[3]);
            *(uint4*)&sn->Al[arow * GSTR + ak0] = make_uint4(l[0], l[1], l[2], l[3]);
            split8(br, h, l);
            *(uint4*)&sn->Bh[bn * GSTR + bk0] = make_uint4(h[0], h[1], h[2], h[3]);
            *(uint4*)&sn->Bl[bn * GSTR + bk0] = make_uint4(l[0], l[1], l[2], l[3]);
        }
        __syncthreads();
    }

    // epilogue: bias + store
#pragma unroll
    for (int i = 0; i < 4; i++) {
        const int row = by * GBM + wm * 64 + i * 16 + gid;
#pragma unroll
        for (int j = 0; j < 4; j++) {
            const int col = bx * GBN + wn * 32 + j * 8 + tig * 2;
            const float b0 = bias[col], b1 = bias[col + 1];
            float2 s0 = make_float2(acc[i][j][0] + b0, acc[i][j][1] + b1);
            float2 s1 = make_float2(acc[i][j][2] + b0, acc[i][j][3] + b1);
            *(float2*)&C[(size_t)row * N + col]       = s0;
            *(float2*)&C[(size_t)(row + 8) * N + col] = s1;
        }
    }
}

// out-projection
__global__ __launch_bounds__(256) void gemm_tc(
    const float* __restrict__ A, const float* __restrict__ B,
    const float* __restrict__ bias, float* __restrict__ C, int N, int K)
{
    __shared__ SmemGemm sm[2];
    gemm_body(A, B, bias, C, N, K, blockIdx.x, blockIdx.y, sm);
}

// fused Q + K + V projections in one launch (shared A = x).
// grid.x: 0..7 -> Q column tiles; 8..9 -> K; 10..11 -> V.
__global__ __launch_bounds__(256) void gemm_qkv(
    const float* __restrict__ x,
    const float* __restrict__ Wq, const float* __restrict__ bq,
    const float* __restrict__ Wk, const float* __restrict__ bk,
    const float* __restrict__ Wv, const float* __restrict__ bv)
{
    __shared__ SmemGemm sm[2];
    const int bx = blockIdx.x;
    if (bx < 8)
        gemm_body(x, Wq, bq, g_q, D_MODEL, D_MODEL, bx, blockIdx.y, sm);
    else if (bx < 10)
        gemm_body(x, Wk, bk, g_k, KVD, D_MODEL, bx - 8, blockIdx.y, sm);
    else
        gemm_body(x, Wv, bv, g_v, KVD, D_MODEL, bx - 10, blockIdx.y, sm);
}

// ================= tensor-core flash attention (windowed, ALiBi, GQA) =================
// R4 structure, fragment loads switched to ldmatrix (64 LDSM vs 256 LDS per tile).
#define ASTR 72

__global__ __launch_bounds__(256) void attn_tc(
    const float* __restrict__ Q, const float* __restrict__ Kg,
    const float* __restrict__ Vg, float* __restrict__ Og)
{
    __shared__ __nv_bfloat16 smKh[64 * ASTR];
    __shared__ __nv_bfloat16 smKl[64 * ASTR];
    __shared__ __nv_bfloat16 smVh[64 * ASTR];   // transposed [d][key]
    __shared__ __nv_bfloat16 smVl[64 * ASTR];

    const int h   = blockIdx.y;
    const int qb  = blockIdx.x * 128;
    const int tid = threadIdx.x;
    const int wid = tid >> 5;
    const int lane = tid & 31;
    const int gid = lane >> 2;
    const int tig = lane & 3;
    const int qw0 = wid * 16;
    const int kvh = h >> 2;
    const float slope2 = exp2f(-0.5f * (float)(h + 1)) * 1.442695041f;
    const float qscale = 0.125f * 1.442695041f;

    // ldmatrix B-operand lane pattern (rows = keys or dims, stride ASTR)
    const int l7    = lane & 7;
    const int b_row = l7 + (lane >> 4) * 8;
    const int b_col = ((lane >> 3) & 1) * 8;
    const unsigned bOff = (unsigned)((b_row * ASTR + b_col) * 2);
    const unsigned shKhB = (unsigned)__cvta_generic_to_shared(smKh) + bOff;
    const unsigned shKlB = (unsigned)__cvta_generic_to_shared(smKl) + bOff;
    const unsigned shVhB = (unsigned)__cvta_generic_to_shared(smVh) + bOff;
    const unsigned shVlB = (unsigned)__cvta_generic_to_shared(smVl) + bOff;

    // stage Q (128x64), pre-scaled, into K/V smem space temporarily
    {
        __nv_bfloat16* Qh = smKh;
        __nv_bfloat16* Ql = smVh;
        for (int u = tid; u < 128 * 16; u += 256) {
            const int r  = u >> 4;
            const int d4 = (u & 15) << 2;
            float4 v = *(const float4*)(Q + (size_t)(qb + r) * D_MODEL + h * HD + d4);
            unsigned h0, l0, h1, l1;
            split2(v.x * qscale, v.y * qscale, h0, l0);
            split2(v.z * qscale, v.w * qscale, h1, l1);
            *(uint2*)&Qh[r * ASTR + d4] = make_uint2(h0, h1);
            *(uint2*)&Ql[r * ASTR + d4] = make_uint2(l0, l1);
        }
        __syncthreads();
    }

    unsigned qh[4][4], ql[4][4];
    {
        const __nv_bfloat16* Qh = smKh;
        const __nv_bfloat16* Ql = smVh;
#pragma unroll
        for (int t = 0; t < 4; t++) {
            const int base = (qw0 + gid) * ASTR + 16 * t + 2 * tig;
            qh[t][0] = lds_u32b(&Qh[base]);
            qh[t][1] = lds_u32b(&Qh[base + 8 * ASTR]);
            qh[t][2] = lds_u32b(&Qh[base + 8]);
            qh[t][3] = lds_u32b(&Qh[base + 8 * ASTR + 8]);
            ql[t][0] = lds_u32b(&Ql[base]);
            ql[t][1] = lds_u32b(&Ql[base + 8 * ASTR]);
            ql[t][2] = lds_u32b(&Ql[base + 8]);
            ql[t][3] = lds_u32b(&Ql[base + 8 * ASTR + 8]);
        }
        __syncthreads();
    }

    float o[8][4];
#pragma unroll
    for (int j = 0; j < 8; j++)
#pragma unroll
        for (int r = 0; r < 4; r++) o[j][r] = 0.f;
    float lsum0 = 0.f, lsum1 = 0.f;

    const int qi0     = qb + qw0 + gid;
    const int q_first = qb + qw0;
    const int q_last  = q_first + 15;

    int kb0 = qb - WINDOW;
    if (kb0 < 0) kb0 = 0;
    const int kbend = qb + 128;

    for (int kb = kb0; kb < kbend; kb += 64) {
        for (int u = tid; u < 64 * 16; u += 256) {
            const int r  = u >> 4;
            const int d4 = (u & 15) << 2;
            float4 v = *(const float4*)(Kg + (size_t)(kb + r) * KVD + kvh * HD + d4);
            unsigned h0, l0, h1, l1;
            split2(v.x, v.y, h0, l0);
            split2(v.z, v.w, h1, l1);
            *(uint2*)&smKh[r * ASTR + d4] = make_uint2(h0, h1);
            *(uint2*)&smKl[r * ASTR + d4] = make_uint2(l0, l1);
        }
        for (int u = tid; u < 2048; u += 256) {
            const int d  = u & 63;
            const int kp = u >> 6;
            const float v0 = Vg[(size_t)(kb + 2 * kp)     * KVD + kvh * HD + d];
            const float v1 = Vg[(size_t)(kb + 2 * kp + 1) * KVD + kvh * HD + d];
            unsigned hh, ll;
            split2(v0, v1, hh, ll);
            *(unsigned*)&smVh[d * ASTR + 2 * kp] = hh;
            *(unsigned*)&smVl[d * ASTR + 2 * kp] = ll;
        }
        __syncthreads();

        const bool active = !(kb > q_last || kb + 63 < q_first - (WINDOW - 1));
        if (active) {
            unsigned ph[8][2], pl[8][2];
            const int dbase = qi0 - kb;
            // ---- S = Q K^T over key pairs (2 j-tiles per LDSM set) ----
#pragma unroll
            for (int jp = 0; jp < 4; jp++) {
                unsigned kh[4][4], kl[4][4];
#pragma unroll
                for (int t = 0; t < 4; t++) {
                    const unsigned off = (unsigned)((16 * jp * ASTR + 16 * t) * 2);
                    ldsm_x4(kh[t], shKhB + off);
                    ldsm_x4(kl[t], shKlB + off);
                }
                float s0[4] = {0.f, 0.f, 0.f, 0.f};
                float s1[4] = {0.f, 0.f, 0.f, 0.f};
#pragma unroll
                for (int t = 0; t < 4; t++) {
                    unsigned bh0[2] = { kh[t][0], kh[t][1] };
                    unsigned bl0[2] = { kl[t][0], kl[t][1] };
                    unsigned bh1[2] = { kh[t][2], kh[t][3] };
                    unsigned bl1[2] = { kl[t][2], kl[t][3] };
                    mma_bf16(s0, qh[t], bh0);
                    mma_bf16(s0, qh[t], bl0);
                    mma_bf16(s0, ql[t], bh0);
                    mma_bf16(s1, qh[t], bh1);
                    mma_bf16(s1, qh[t], bl1);
                    mma_bf16(s1, ql[t], bh1);
                }
                // j = 2*jp
                {
                    const int d00 = dbase - 16 * jp - 2 * tig;
                    const int d01 = d00 - 1, d10 = d00 + 8, d11 = d00 + 7;
                    float p00 = ((unsigned)d00 < WINDOW) ? ex2(fmaf(-slope2, (float)d00, s0[0])) : 0.f;
                    float p01 = ((unsigned)d01 < WINDOW) ? ex2(fmaf(-slope2, (float)d01, s0[1])) : 0.f;
                    float p10 = ((unsigned)d10 < WINDOW) ? ex2(fmaf(-slope2, (float)d10, s0[2])) : 0.f;
                    float p11 = ((unsigned)d11 < WINDOW) ? ex2(fmaf(-slope2, (float)d11, s0[3])) : 0.f;
                    lsum0 += p00 + p01;
                    lsum1 += p10 + p11;
                    split2(p00, p01, ph[2*jp][0], pl[2*jp][0]);
                    split2(p10, p11, ph[2*jp][1], pl[2*jp][1]);
                }
                // j = 2*jp + 1
                {
                    const int d00 = dbase - 16 * jp - 8 - 2 * tig;
                    const int d01 = d00 - 1, d10 = d00 + 8, d11 = d00 + 7;
                    float p00 = ((unsigned)d00 < WINDOW) ? ex2(fmaf(-slope2, (float)d00, s1[0])) : 0.f;
                    float p01 = ((unsigned)d01 < WINDOW) ? ex2(fmaf(-slope2, (float)d01, s1[1])) : 0.f;
                    float p10 = ((unsigned)d10 < WINDOW) ? ex2(fmaf(-slope2, (float)d10, s1[2])) : 0.f;
                    float p11 = ((unsigned)d11 < WINDOW) ? ex2(fmaf(-slope2, (float)d11, s1[3])) : 0.f;
                    lsum0 += p00 + p01;
                    lsum1 += p10 + p11;
                    split2(p00, p01, ph[2*jp+1][0], pl[2*jp+1][0]);
                    split2(p10, p11, ph[2*jp+1][1], pl[2*jp+1][1]);
                }
            }

            // ---- O += P V ----
#pragma unroll
            for (int t = 0; t < 4; t++) {
                unsigned ah[4] = { ph[2*t][0], ph[2*t][1], ph[2*t+1][0], ph[2*t+1][1] };
                unsigned al[4] = { pl[2*t][0], pl[2*t][1], pl[2*t+1][0], pl[2*t+1][1] };
#pragma unroll
                for (int jdp = 0; jdp < 4; jdp++) {
                    const unsigned off = (unsigned)((16 * jdp * ASTR + 16 * t) * 2);
                    unsigned vh[4], vl[4];
                    ldsm_x4(vh, shVhB + off);
                    ldsm_x4(vl, shVlB + off);
                    unsigned bh0[2] = { vh[0], vh[1] };
                    unsigned bl0[2] = { vl[0], vl[1] };
                    unsigned bh1[2] = { vh[2], vh[3] };
                    unsigned bl1[2] = { vl[2], vl[3] };
                    mma_bf16(o[2*jdp],   ah, bh0);
                    mma_bf16(o[2*jdp],   ah, bl0);
                    mma_bf16(o[2*jdp],   al, bh0);
                    mma_bf16(o[2*jdp+1], ah, bh1);
                    mma_bf16(o[2*jdp+1], ah, bl1);
                    mma_bf16(o[2*jdp+1], al, bh1);
                }
            }
        }
        __syncthreads();
    }

    lsum0 += __shfl_xor_sync(0xffffffffu, lsum0, 1);
    lsum0 += __shfl_xor_sync(0xffffffffu, lsum0, 2);
    lsum1 += __shfl_xor_sync(0xffffffffu, lsum1, 1);
    lsum1 += __shfl_xor_sync(0xffffffffu, lsum1, 2);
    const float inv0 = 1.f / lsum0;
    const float inv1 = 1.f / lsum1;

    const int row0 = qi0;
#pragma unroll
    for (int jd = 0; jd < 8; jd++) {
        const int col = h * HD + 8 * jd + 2 * tig;
        float2 s0 = make_float2(o[jd][0] * inv0, o[jd][1] * inv0);
        float2 s1 = make_float2(o[jd][2] * inv1, o[jd][3] * inv1);
        *(float2*)&Og[(size_t)row0 * D_MODEL + col]       = s0;
        *(float2*)&Og[(size_t)(row0 + 8) * D_MODEL + col] = s1;
    }
}

// ---------------- launch ----------------
extern "C" void kernel_launch(void* const* d_in, const int* in_sizes, int n_in,
                              void* d_out, int out_size)
{
    const float* x  = (const float*)d_in[0];
    const float* Wq = (const float*)d_in[1];
    const float* bq = (const float*)d_in[2];
    const float* Wk = (const float*)d_in[3];
    const float* bk = (const float*)d_in[4];
    const float* Wv = (const float*)d_in[5];
    const float* bv = (const float*)d_in[6];
    const float* Wo = (const float*)d_in[7];
    const float* bo = (const float*)d_in[8];
    float* out = (float*)d_out;

    float *q, *k, *v, *attn;
    cudaGetSymbolAddress((void**)&q,    g_q);
    cudaGetSymbolAddress((void**)&k,    g_k);
    cudaGetSymbolAddress((void**)&v,    g_v);
    cudaGetSymbolAddress((void**)&attn, g_attn);

    // fused Q+K+V projections: grid (12, 32)
    dim3 gQkv(12, T_SEQ / GBM);
    gemm_qkv<<<gQkv, 256>>>(x, Wq, bq, Wk, bk, Wv, bv);

    dim3 gAttn(T_SEQ / 128, NHEADS);         // (32, 16)
    attn_tc<<<gAttn, 256>>>(q, k, v, attn);

    // out projection: grid (8, 32)
    dim3 gOut(D_MODEL / GBN, T_SEQ / GBM);
    gemm_tc<<<gOut, 256>>>(attn, Wo, bo, out, D_MODEL, D_MODEL);
}